// round 4
// baseline (speedup 1.0000x reference)
#include <cuda_runtime.h>

// ============================================================================
// QCNN 8-qubit circuit — exact algebraic reduction to a 3x3 bilinear form.
//
// CNOTs only couple disjoint qubit pairs; <Z_0> depends only on the (0,1)
// 2-qubit subsystem. Parameterized gates are batch-independent -> the 3-layer
// 2-qubit circuit is one fixed 4x4 complex unitary W, and with real input
// state psi0, z = psi0^T S psi0, S = Re(W^H diag(1,1,-1,-1) W) (real sym 4x4).
// Since psi0 = (c0,s0)x(c1,s1) with c=cos(x/2), s=sin(x/2), double-angle
// identities collapse z to:
//       z = (1, cos x0, sin x0) · M · (1, cos x1, sin x1)^T,   M real 3x3.
// Per element: 2x __sincosf + 9 FMA + sigmoid.
// ============================================================================

struct Cx { float re, im; };

__device__ __forceinline__ Cx cmul(Cx a, Cx b) {
    return { a.re * b.re - a.im * b.im, a.re * b.im + a.im * b.re };
}

// Per-warp, barrier-free: build W via lane-parallel shuffles, reduce to S,
// then to the 3x3 bilinear form M (every lane ends with full M).
__device__ __forceinline__ void build_M(const float* __restrict__ params,
                                        float (&M)[3][3]) {
    const unsigned FULL = 0xFFFFFFFFu;
    int lane = threadIdx.x & 31;
    int r = (lane >> 2) & 3;
    int c = lane & 3;

    Cx w = { (r == c) ? 1.0f : 0.0f, 0.0f };

    #pragma unroll
    for (int l = 0; l < 3; l++) {
        Cx U[2][2][2];
        #pragma unroll
        for (int q = 0; q < 2; q++) {
            float a = params[(l * 8 + q) * 3 + 0];
            float b = params[(l * 8 + q) * 3 + 1];
            float g = params[(l * 8 + q) * 3 + 2];
            float sb, cb;  __sincosf(0.5f * b, &sb, &cb);
            float sp, cp;  __sincosf(0.5f * (a + g), &sp, &cp);
            float sm, cm;  __sincosf(0.5f * (a - g), &sm, &cm);
            U[q][0][0] = {  cb * cp, -cb * sp };
            U[q][0][1] = { -sb * cm, -sb * sm };
            U[q][1][0] = {  sb * cm, -sb * sm };
            U[q][1][1] = {  cb * cp,  cb * sp };
        }

        // K row r of (U0 (x) U1)
        Cx K[4];
        #pragma unroll
        for (int k = 0; k < 4; k++)
            K[k] = cmul(U[0][r >> 1][k >> 1], U[1][r & 1][k & 1]);

        // T[r][c] = sum_k K[r][k] * W[k][c]
        Cx acc = { 0.0f, 0.0f };
        #pragma unroll
        for (int k = 0; k < 4; k++) {
            Cx wk;
            wk.re = __shfl_sync(FULL, w.re, k * 4 + c);
            wk.im = __shfl_sync(FULL, w.im, k * 4 + c);
            Cx p = cmul(K[k], wk);
            acc.re += p.re;  acc.im += p.im;
        }

        // CNOT(wire0->wire1): swap rows 2<->3.
        int sr = (r >= 2) ? (5 - r) : r;
        w.re = __shfl_sync(FULL, acc.re, sr * 4 + c);
        w.im = __shfl_sync(FULL, acc.im, sr * 4 + c);
    }

    // Broadcast W to every lane.
    float Wre[4][4], Wim[4][4];
    #pragma unroll
    for (int k = 0; k < 16; k++) {
        Wre[k >> 2][k & 3] = __shfl_sync(FULL, w.re, k);
        Wim[k >> 2][k & 3] = __shfl_sync(FULL, w.im, k);
    }

    // S[a][b] = sum_r d_r Re(conj(W[r][a]) W[r][b]), d=(1,1,-1,-1). Only the
    // entries feeding M are needed: diagonal + (01,23,02,13,03,12).
    float S[4][4];
    #pragma unroll
    for (int a = 0; a < 4; a++)
        #pragma unroll
        for (int b = a; b < 4; b++) {
            float s = 0.0f;
            #pragma unroll
            for (int rr = 0; rr < 4; rr++) {
                float t = fmaf(Wre[rr][a], Wre[rr][b], Wim[rr][a] * Wim[rr][b]);
                s += (rr < 2) ? t : -t;
            }
            S[a][b] = s;
        }

    // M from S (double-angle reduction), rows indexed by (1, cos x0, sin x0),
    // cols by (1, cos x1, sin x1).
    M[0][0] = 0.25f * (S[0][0] + S[1][1] + S[2][2] + S[3][3]);
    M[1][0] = 0.25f * (S[0][0] + S[1][1] - S[2][2] - S[3][3]);
    M[0][1] = 0.25f * (S[0][0] - S[1][1] + S[2][2] - S[3][3]);
    M[1][1] = 0.25f * (S[0][0] - S[1][1] - S[2][2] + S[3][3]);
    M[2][0] = 0.5f  * (S[0][2] + S[1][3]);
    M[2][1] = 0.5f  * (S[0][2] - S[1][3]);
    M[0][2] = 0.5f  * (S[0][1] + S[2][3]);
    M[1][2] = 0.5f  * (S[0][1] - S[2][3]);
    M[2][2] = 0.5f  * (S[0][3] + S[1][2]);
}

__global__ void __launch_bounds__(256) qcnn_fused_kernel(
    const float* __restrict__ x,
    const float* __restrict__ params,
    const float* __restrict__ weight,
    float* __restrict__ out,
    int n)
{
    int i = blockIdx.x * blockDim.x + threadIdx.x;

    // Issue the data load first; everything below overlaps its latency.
    float2 xv = make_float2(0.0f, 0.0f);
    if (i < n)
        xv = *reinterpret_cast<const float2*>(x + (size_t)i * 8);
    float wgt = __ldg(weight);

    // Per-element trig is independent of the build chain — hoisted ahead.
    float S0, C0, S1, C1;
    __sincosf(xv.x, &S0, &C0);
    __sincosf(xv.y, &S1, &C1);

    // Per-warp, barrier-free 3x3 bilinear form.
    float M[3][3];
    build_M(params, M);

    if (i >= n) return;

    // z = (1,C0,S0) M (1,C1,S1)^T  — 8 FMA tail after M is ready.
    float t0 = fmaf(M[0][2], S1, fmaf(M[0][1], C1, M[0][0]));
    float t1 = fmaf(M[1][2], S1, fmaf(M[1][1], C1, M[1][0]));
    float t2 = fmaf(M[2][2], S1, fmaf(M[2][1], C1, M[2][0]));
    float z  = fmaf(S0, t2, fmaf(C0, t1, t0));

    out[i] = __fdividef(1.0f, 1.0f + __expf(-wgt * z));
}

extern "C" void kernel_launch(void* const* d_in, const int* in_sizes, int n_in,
                              void* d_out, int out_size) {
    const float* x      = (const float*)d_in[0];   // (65536, 8) fp32
    const float* params = (const float*)d_in[1];   // (3, 8, 3) fp32
    const float* weight = (const float*)d_in[2];   // scalar fp32
    float* out = (float*)d_out;                    // (65536,) fp32

    int n = in_sizes[0] / 8;                       // 65536

    int threads = 256;
    int blocks = (n + threads - 1) / threads;      // 256 blocks
    qcnn_fused_kernel<<<blocks, threads>>>(x, params, weight, out, n);
}

// round 5
// speedup vs baseline: 1.0987x; 1.0987x over previous
#include <cuda_runtime.h>

// ============================================================================
// QCNN 8-qubit circuit — exact algebraic reduction to a 3x3 bilinear form,
// two kernels overlapped via Programmatic Dependent Launch (PDL).
//
// Math (established R1-R4): CNOTs couple only disjoint qubit pairs; <Z_0>
// depends only on the (0,1) 2-qubit subsystem; batch-independent params make
// the 3-layer circuit one fixed 4x4 complex unitary W; with real product
// input state and double-angle identities:
//     z   = (1, cos x0, sin x0) · M · (1, cos x1, sin x1)^T,  M real 3x3
//     out = sigmoid(weight * z)         (weight folded into M here)
//
// Structure: tiny primary kernel builds M (warp-cooperative) and writes it to
// a __device__ global; the big secondary kernel launches concurrently (PDL),
// does its x-loads + trig during the primary's execution, then
// griddepcontrol.wait's before reading M. No per-warp build cost, no
// serialized second graph node.
// ============================================================================

__device__ float4 g_M[3];   // (M00,M01,M02,M10) (M11,M12,M20,M21) (M22,-,-,-)

struct Cx { float re, im; };

__device__ __forceinline__ Cx cmul(Cx a, Cx b) {
    return { a.re * b.re - a.im * b.im, a.re * b.im + a.im * b.re };
}

// ----------------------------------------------------------------------------
// Primary: build M from params (warp-cooperative, 1 warp).
// ----------------------------------------------------------------------------
__global__ void build_M_kernel(const float* __restrict__ params,
                               const float* __restrict__ weight) {
    // Let the dependent (main) kernel start ramping immediately.
    asm volatile("griddepcontrol.launch_dependents;");

    const unsigned FULL = 0xFFFFFFFFu;
    int lane = threadIdx.x & 31;
    int r = (lane >> 2) & 3;
    int c = lane & 3;

    Cx w = { (r == c) ? 1.0f : 0.0f, 0.0f };

    #pragma unroll
    for (int l = 0; l < 3; l++) {
        // U[q] = Rz(g) Ry(b) Rz(a)
        Cx U[2][2][2];
        #pragma unroll
        for (int q = 0; q < 2; q++) {
            float a = params[(l * 8 + q) * 3 + 0];
            float b = params[(l * 8 + q) * 3 + 1];
            float g = params[(l * 8 + q) * 3 + 2];
            float sb, cb;  __sincosf(0.5f * b, &sb, &cb);
            float sp, cp;  __sincosf(0.5f * (a + g), &sp, &cp);
            float sm, cm;  __sincosf(0.5f * (a - g), &sm, &cm);
            U[q][0][0] = {  cb * cp, -cb * sp };
            U[q][0][1] = { -sb * cm, -sb * sm };
            U[q][1][0] = {  sb * cm, -sb * sm };
            U[q][1][1] = {  cb * cp,  cb * sp };
        }

        // K row r of (U0 (x) U1)
        Cx K[4];
        #pragma unroll
        for (int k = 0; k < 4; k++)
            K[k] = cmul(U[0][r >> 1][k >> 1], U[1][r & 1][k & 1]);

        // T[r][c] = sum_k K[r][k] * W[k][c]
        Cx acc = { 0.0f, 0.0f };
        #pragma unroll
        for (int k = 0; k < 4; k++) {
            Cx wk;
            wk.re = __shfl_sync(FULL, w.re, k * 4 + c);
            wk.im = __shfl_sync(FULL, w.im, k * 4 + c);
            Cx p = cmul(K[k], wk);
            acc.re += p.re;  acc.im += p.im;
        }

        // CNOT(wire0->wire1): swap rows 2<->3.
        int sr = (r >= 2) ? (5 - r) : r;
        w.re = __shfl_sync(FULL, acc.re, sr * 4 + c);
        w.im = __shfl_sync(FULL, acc.im, sr * 4 + c);
    }

    // Broadcast W to every lane.
    float Wre[4][4], Wim[4][4];
    #pragma unroll
    for (int k = 0; k < 16; k++) {
        Wre[k >> 2][k & 3] = __shfl_sync(FULL, w.re, k);
        Wim[k >> 2][k & 3] = __shfl_sync(FULL, w.im, k);
    }

    if (lane != 0) return;

    // S[a][b] = sum_r d_r Re(conj(W[r][a]) W[r][b]), d=(1,1,-1,-1)
    float S[4][4];
    #pragma unroll
    for (int a = 0; a < 4; a++)
        #pragma unroll
        for (int b = a; b < 4; b++) {
            float s = 0.0f;
            #pragma unroll
            for (int rr = 0; rr < 4; rr++) {
                float t = fmaf(Wre[rr][a], Wre[rr][b], Wim[rr][a] * Wim[rr][b]);
                s += (rr < 2) ? t : -t;
            }
            S[a][b] = s;
        }

    float wg = weight[0];

    // 3x3 bilinear form, weight folded in.
    float M00 = wg * 0.25f * (S[0][0] + S[1][1] + S[2][2] + S[3][3]);
    float M10 = wg * 0.25f * (S[0][0] + S[1][1] - S[2][2] - S[3][3]);
    float M01 = wg * 0.25f * (S[0][0] - S[1][1] + S[2][2] - S[3][3]);
    float M11 = wg * 0.25f * (S[0][0] - S[1][1] - S[2][2] + S[3][3]);
    float M20 = wg * 0.5f  * (S[0][2] + S[1][3]);
    float M21 = wg * 0.5f  * (S[0][2] - S[1][3]);
    float M02 = wg * 0.5f  * (S[0][1] + S[2][3]);
    float M12 = wg * 0.5f  * (S[0][1] - S[2][3]);
    float M22 = wg * 0.5f  * (S[0][3] + S[1][2]);

    g_M[0] = make_float4(M00, M01, M02, M10);
    g_M[1] = make_float4(M11, M12, M20, M21);
    g_M[2] = make_float4(M22, 0.0f, 0.0f, 0.0f);
}

// ----------------------------------------------------------------------------
// Secondary (PDL): one thread per batch element. Loads + trig run concurrently
// with the primary; griddepcontrol.wait guards the read of g_M.
// ----------------------------------------------------------------------------
__global__ void __launch_bounds__(256) qcnn_main_kernel(
    const float* __restrict__ x,
    float* __restrict__ out,
    int n)
{
    int i = blockIdx.x * blockDim.x + threadIdx.x;

    float2 xv = make_float2(0.0f, 0.0f);
    if (i < n)
        xv = *reinterpret_cast<const float2*>(x + (size_t)i * 8);

    float S0, C0, S1, C1;
    __sincosf(xv.x, &S0, &C0);
    __sincosf(xv.y, &S1, &C1);

    // Wait for primary grid completion (makes g_M writes visible).
    asm volatile("griddepcontrol.wait;" ::: "memory");

    float4 m0 = g_M[0];
    float4 m1 = g_M[1];
    float4 m2 = g_M[2];

    if (i >= n) return;

    // z = (1,C0,S0) M (1,C1,S1)^T   (weight already folded into M)
    float t0 = fmaf(m0.z, S1, fmaf(m0.y, C1, m0.x));
    float t1 = fmaf(m1.y, S1, fmaf(m1.x, C1, m0.w));
    float t2 = fmaf(m2.x, S1, fmaf(m1.w, C1, m1.z));
    float z  = fmaf(S0, t2, fmaf(C0, t1, t0));

    out[i] = __fdividef(1.0f, 1.0f + __expf(-z));
}

// ----------------------------------------------------------------------------
// Launch: primary (build) + PDL secondary (main), default stream, capturable.
// ----------------------------------------------------------------------------
extern "C" void kernel_launch(void* const* d_in, const int* in_sizes, int n_in,
                              void* d_out, int out_size) {
    const float* x      = (const float*)d_in[0];   // (65536, 8) fp32
    const float* params = (const float*)d_in[1];   // (3, 8, 3) fp32
    const float* weight = (const float*)d_in[2];   // scalar fp32
    float* out = (float*)d_out;                    // (65536,) fp32

    int n = in_sizes[0] / 8;                       // 65536

    // Primary: tiny build kernel.
    {
        cudaLaunchConfig_t cfg = {};
        cfg.gridDim  = dim3(1, 1, 1);
        cfg.blockDim = dim3(32, 1, 1);
        cfg.dynamicSmemBytes = 0;
        cfg.stream = 0;
        cudaLaunchKernelEx(&cfg, build_M_kernel, params, weight);
    }

    // Secondary: main kernel with programmatic stream serialization (PDL).
    {
        cudaLaunchConfig_t cfg = {};
        cfg.gridDim  = dim3((n + 255) / 256, 1, 1);   // 256 blocks
        cfg.blockDim = dim3(256, 1, 1);
        cfg.dynamicSmemBytes = 0;
        cfg.stream = 0;

        cudaLaunchAttribute attrs[1];
        attrs[0].id = cudaLaunchAttributeProgrammaticStreamSerialization;
        attrs[0].val.programmaticStreamSerializationAllowed = 1;
        cfg.attrs = attrs;
        cfg.numAttrs = 1;

        cudaLaunchKernelEx(&cfg, qcnn_main_kernel, x, out, n);
    }
}

// round 6
// speedup vs baseline: 1.2564x; 1.1436x over previous
#include <cuda_runtime.h>

// ============================================================================
// QCNN 8-qubit circuit — exact algebraic reduction to a 3x3 bilinear form,
// SINGLE fused kernel (two-node graphs measured +2..4us overhead).
//
// Math (verified R1-R5, rel_err ~1e-7): CNOTs couple only disjoint qubit
// pairs; <Z_0> depends only on the (0,1) 2-qubit subsystem; batch-independent
// params make the 3-layer circuit one fixed 4x4 complex unitary W; with the
// real product input state and double-angle identities:
//     z   = (1, cos x0, sin x0) · M · (1, cos x1, sin x1)^T,  M real 3x3
//     out = sigmoid(weight * z)      (weight folded into M)
//
// Build strategy (warp 0 only, ~500cy post-params, hidden behind the other
// warps' x-load latency):
//   - 18 sincos done lane-parallel (lanes 0..17, ~2 SIMD MUFU issues)
//   - CNOT folded into K's row index (sr); W0 = I kills layer-0 exchange
//   - 2 smem exchange rounds, triple-buffered, 1 __syncwarp each
//   - S computed lane-parallel (lane a*4+b), gathered via shfl broadcasts
// ============================================================================

__global__ void __launch_bounds__(256) qcnn_fused_kernel(
    const float* __restrict__ x,
    const float* __restrict__ params,
    const float* __restrict__ weight,
    float* __restrict__ out,
    int n)
{
    __shared__ float sTrig[3][12];          // per layer: w0 cb,sb,cp,sp,cm,sm; w1 same
    __shared__ float sWre[3][16], sWim[3][16];
    __shared__ float sM[9];

    int tid = threadIdx.x;
    int i = blockIdx.x * 256 + tid;

    // Issue the batch-data load first; everything overlaps its ~600cy latency.
    float2 xv = make_float2(0.0f, 0.0f);
    if (i < n)
        xv = *reinterpret_cast<const float2*>(x + (size_t)i * 8);

    if (tid < 32) {
        const unsigned FULL = 0xFFFFFFFFu;
        int lane = tid;

        // ---- lane-parallel trig: 18 angles, one per lane -------------------
        if (lane < 18) {
            int l = lane / 6, rem = lane - l * 6;
            int q = rem / 3, combo = rem - q * 3;
            const float* p = params + l * 24 + q * 3;   // a,b,g contiguous
            float ang;
            if (combo == 0)      ang = 0.5f * p[1];              // b/2
            else if (combo == 1) ang = 0.5f * (p[0] + p[2]);     // (a+g)/2
            else                 ang = 0.5f * (p[0] - p[2]);     // (a-g)/2
            float s, c;
            __sincosf(ang, &s, &c);
            sTrig[l][q * 6 + combo * 2 + 0] = c;
            sTrig[l][q * 6 + combo * 2 + 1] = s;
        }
        float wgt = __ldg(weight);
        __syncwarp();

        // ---- W chain: lanes 0..15 own element (r,c); CNOT folded via sr ----
        int r = (lane >> 2) & 3, c = lane & 3;
        int sr = (r >= 2) ? (5 - r) : r;        // 0,1,3,2
        int i0 = sr >> 1, i1 = sr & 1;

        float wre = 0.0f, wim = 0.0f;
        #pragma unroll
        for (int l = 0; l < 3; l++) {
            float cb0 = sTrig[l][0],  sb0 = sTrig[l][1];
            float cp0 = sTrig[l][2],  sp0 = sTrig[l][3];
            float cm0 = sTrig[l][4],  sm0 = sTrig[l][5];
            float cb1 = sTrig[l][6],  sb1 = sTrig[l][7];
            float cp1 = sTrig[l][8],  sp1 = sTrig[l][9];
            float cm1 = sTrig[l][10], sm1 = sTrig[l][11];

            // Row i0 of U0, row i1 of U1:
            // row0 = [( cb*cp, -cb*sp), (-sb*cm, -sb*sm)]
            // row1 = [( sb*cm, -sb*sm), ( cb*cp,  cb*sp)]
            float a0r, a0i, a1r, a1i;        // U0[i0][0], U0[i0][1]
            if (i0 == 0) { a0r =  cb0*cp0; a0i = -cb0*sp0; a1r = -sb0*cm0; a1i = -sb0*sm0; }
            else         { a0r =  sb0*cm0; a0i = -sb0*sm0; a1r =  cb0*cp0; a1i =  cb0*sp0; }
            float b0r, b0i, b1r, b1i;        // U1[i1][0], U1[i1][1]
            if (i1 == 0) { b0r =  cb1*cp1; b0i = -cb1*sp1; b1r = -sb1*cm1; b1i = -sb1*sm1; }
            else         { b0r =  sb1*cm1; b0i = -sb1*sm1; b1r =  cb1*cp1; b1i =  cb1*sp1; }

            // K_eff[k] = U0[i0][k>>1] * U1[i1][k&1]
            float Kre[4], Kim[4];
            Kre[0] = a0r*b0r - a0i*b0i;  Kim[0] = a0r*b0i + a0i*b0r;
            Kre[1] = a0r*b1r - a0i*b1i;  Kim[1] = a0r*b1i + a0i*b1r;
            Kre[2] = a1r*b0r - a1i*b0i;  Kim[2] = a1r*b0i + a1i*b0r;
            Kre[3] = a1r*b1r - a1i*b1i;  Kim[3] = a1r*b1i + a1i*b1r;

            if (l == 0) {
                // W_prev = I: W_new[r][c] = K_eff[c]
                wre = Kre[c];  wim = Kim[c];
            } else {
                // Exchange through buffer l (triple-buffered: no pre-sync).
                if (lane < 16) { sWre[l][lane] = wre; sWim[l][lane] = wim; }
                __syncwarp();
                float ar = 0.0f, ai = 0.0f;
                #pragma unroll
                for (int k = 0; k < 4; k++) {
                    float br = sWre[l][k * 4 + c], bi = sWim[l][k * 4 + c];
                    ar = fmaf(Kre[k], br, fmaf(-Kim[k], bi, ar));
                    ai = fmaf(Kre[k], bi, fmaf( Kim[k], br, ai));
                }
                wre = ar;  wim = ai;
            }
        }

        // Final W into buffer 0 (untouched so far -> no pre-sync needed).
        if (lane < 16) { sWre[0][lane] = wre; sWim[0][lane] = wim; }
        __syncwarp();

        // ---- lane-parallel S: lane a*4+b computes S[a][b] ------------------
        // S[a][b] = sum_r d_r (Wre[r][a]Wre[r][b] + Wim[r][a]Wim[r][b]),
        // d = (+,+,-,-)
        int a = (lane >> 2) & 3, b = lane & 3;
        float s_ab = 0.0f;
        #pragma unroll
        for (int rr = 0; rr < 4; rr++) {
            float t = fmaf(sWre[0][rr * 4 + a], sWre[0][rr * 4 + b],
                           sWim[0][rr * 4 + a] * sWim[0][rr * 4 + b]);
            s_ab += (rr < 2) ? t : -t;
        }

        // Gather the 10 needed S entries to every lane (shfl broadcasts).
        float s00 = __shfl_sync(FULL, s_ab, 0);
        float s11 = __shfl_sync(FULL, s_ab, 5);
        float s22 = __shfl_sync(FULL, s_ab, 10);
        float s33 = __shfl_sync(FULL, s_ab, 15);
        float s01 = __shfl_sync(FULL, s_ab, 1);
        float s23 = __shfl_sync(FULL, s_ab, 11);
        float s02 = __shfl_sync(FULL, s_ab, 2);
        float s13 = __shfl_sync(FULL, s_ab, 7);
        float s03 = __shfl_sync(FULL, s_ab, 3);
        float s12 = __shfl_sync(FULL, s_ab, 6);

        if (lane == 0) {
            float q4 = 0.25f * wgt, q2 = 0.5f * wgt;
            sM[0] = q4 * (s00 + s11 + s22 + s33);   // M00
            sM[1] = q4 * (s00 - s11 + s22 - s33);   // M01
            sM[2] = q2 * (s01 + s23);               // M02
            sM[3] = q4 * (s00 + s11 - s22 - s33);   // M10
            sM[4] = q4 * (s00 - s11 - s22 + s33);   // M11
            sM[5] = q2 * (s01 - s23);               // M12
            sM[6] = q2 * (s02 + s13);               // M20
            sM[7] = q2 * (s02 - s13);               // M21
            sM[8] = q2 * (s03 + s12);               // M22
        }
    }

    // Per-element trig — independent of the build; overlaps warp 0's work.
    float S0, C0, S1, C1;
    __sincosf(xv.x, &S0, &C0);
    __sincosf(xv.y, &S1, &C1);

    __syncthreads();

    float m00 = sM[0], m01 = sM[1], m02 = sM[2];
    float m10 = sM[3], m11 = sM[4], m12 = sM[5];
    float m20 = sM[6], m21 = sM[7], m22 = sM[8];

    if (i >= n) return;

    // z = (1,C0,S0) M (1,C1,S1)^T   (weight already folded into M)
    float t0 = fmaf(m02, S1, fmaf(m01, C1, m00));
    float t1 = fmaf(m12, S1, fmaf(m11, C1, m10));
    float t2 = fmaf(m22, S1, fmaf(m21, C1, m20));
    float z  = fmaf(S0, t2, fmaf(C0, t1, t0));

    out[i] = __fdividef(1.0f, 1.0f + __expf(-z));
}

extern "C" void kernel_launch(void* const* d_in, const int* in_sizes, int n_in,
                              void* d_out, int out_size) {
    const float* x      = (const float*)d_in[0];   // (65536, 8) fp32
    const float* params = (const float*)d_in[1];   // (3, 8, 3) fp32
    const float* weight = (const float*)d_in[2];   // scalar fp32
    float* out = (float*)d_out;                    // (65536,) fp32

    int n = in_sizes[0] / 8;                       // 65536

    int threads = 256;
    int blocks = (n + threads - 1) / threads;      // 256 blocks
    qcnn_fused_kernel<<<blocks, threads>>>(x, params, weight, out, n);
}